// round 2
// baseline (speedup 1.0000x reference)
#include <cuda_runtime.h>
#include <math.h>
#include <stdint.h>

#define S_  256
#define B_  64
#define E_  300
#define H_  512
#define G3  1536          // 3*H
#define NCLS 21
#define NBLK_SCAN 128     // persistent blocks (<=148 SMs, 1/SM via smem => all resident)

// ---------------- scratch (device globals; no allocation allowed) ----------------
__device__ float g_gi_f[(size_t)S_ * B_ * G3];   // [s][b][1536]  (m = s*64+b major)
__device__ float g_gi_b[(size_t)S_ * B_ * G3];   // backward, time-reversed storage
__device__ float g_hf[(size_t)S_ * B_ * H_];     // [s][b][512]
__device__ float g_hb[(size_t)S_ * B_ * H_];     // scan-time order (orig pos = S-1-t)
__device__ unsigned g_bar_count;                 // zero-init at module load
__device__ unsigned g_bar_gen;

// =================================================================================
// Kernel A: gi = gather(emb, idx) @ W_ih^T + b_ih   for both directions
// M=16384, N=3072 (0..1535 fwd, 1536..3071 bwd), K=300. 128x128 tile, BK=8.
// =================================================================================
__global__ void __launch_bounds__(256, 2) gi_gemm_kernel(
    const int* __restrict__ idxmat,      // [B,S]
    const float* __restrict__ emb,       // [V,E]
    const float* __restrict__ Wf,        // [1536,300]
    const float* __restrict__ bf,        // [1536]
    const float* __restrict__ Wb,        // [1536,300]
    const float* __restrict__ bbias)     // [1536]
{
    __shared__ float As[8][128];
    __shared__ float Bs[8][128];

    const int t    = threadIdx.x;
    const int n0   = blockIdx.x * 128;   // 0..23 n-blocks
    const int m0   = blockIdx.y * 128;   // 0..127 m-blocks
    const bool bwd = (n0 >= G3);

    // A gather row
    const int ar = t >> 1;
    const int ak = (t & 1) * 4;
    const int m  = m0 + ar;
    const int srow = m >> 6, brow = m & 63;
    const float* arow = emb + (size_t)idxmat[brow * S_ + srow] * E_;

    // B row (weight row, we read its K dim)
    const int br = t >> 1;
    const int bk = ak;
    const int ng = n0 + br;
    const float* wrow = bwd ? (Wb + (size_t)(ng - G3) * E_)
                            : (Wf + (size_t)ng * E_);

    float acc[8][8];
#pragma unroll
    for (int i = 0; i < 8; i++)
#pragma unroll
        for (int j = 0; j < 8; j++) acc[i][j] = 0.f;

    const int tx = t & 15, ty = t >> 4;

    for (int k0 = 0; k0 < E_; k0 += 8) {
        float4 av = make_float4(0.f, 0.f, 0.f, 0.f);
        float4 bv = make_float4(0.f, 0.f, 0.f, 0.f);
        if (k0 + ak < E_) av = *(const float4*)(arow + k0 + ak);
        if (k0 + bk < E_) bv = *(const float4*)(wrow + k0 + bk);
        __syncthreads();
        As[ak + 0][ar] = av.x; As[ak + 1][ar] = av.y;
        As[ak + 2][ar] = av.z; As[ak + 3][ar] = av.w;
        Bs[bk + 0][br] = bv.x; Bs[bk + 1][br] = bv.y;
        Bs[bk + 2][br] = bv.z; Bs[bk + 3][br] = bv.w;
        __syncthreads();
#pragma unroll
        for (int k = 0; k < 8; k++) {
            float a[8], b[8];
            *(float4*)&a[0] = *(const float4*)&As[k][ty * 4];
            *(float4*)&a[4] = *(const float4*)&As[k][64 + ty * 4];
            *(float4*)&b[0] = *(const float4*)&Bs[k][tx * 4];
            *(float4*)&b[4] = *(const float4*)&Bs[k][64 + tx * 4];
#pragma unroll
            for (int i = 0; i < 8; i++)
#pragma unroll
                for (int j = 0; j < 8; j++)
                    acc[i][j] = fmaf(a[i], b[j], acc[i][j]);
        }
    }

    const float* bias = bwd ? bbias : bf;
    float* gbase = bwd ? g_gi_b : g_gi_f;
    const int nc0 = (bwd ? n0 - G3 : n0) + tx * 4;

#pragma unroll
    for (int i = 0; i < 8; i++) {
        const int mi = m0 + ((i < 4) ? (ty * 4 + i) : (64 + ty * 4 + i - 4));
        const int si = mi >> 6, bi = mi & 63;
        const size_t mrow = bwd ? ((size_t)(S_ - 1 - si) * B_ + bi) : (size_t)mi;
        float* dst = gbase + mrow * G3;
        float4 v0, v1;
        v0.x = acc[i][0] + bias[nc0 + 0];
        v0.y = acc[i][1] + bias[nc0 + 1];
        v0.z = acc[i][2] + bias[nc0 + 2];
        v0.w = acc[i][3] + bias[nc0 + 3];
        v1.x = acc[i][4] + bias[nc0 + 64 + 0];
        v1.y = acc[i][5] + bias[nc0 + 64 + 1];
        v1.z = acc[i][6] + bias[nc0 + 64 + 2];
        v1.w = acc[i][7] + bias[nc0 + 64 + 3];
        *(float4*)(dst + nc0)      = v0;
        *(float4*)(dst + nc0 + 64) = v1;
    }
}

// =================================================================================
// Kernel B: persistent bidirectional GRU scan.
// 128 blocks: blocks 0..63 forward, 64..127 backward. Block owns 8 hidden units j
// => 24 W_hh rows (r/z/n) cached in smem. Per step: stage h (transposed, pitch 65),
// GEMM gh = Ws @ h, gate-combine, write h, grid barrier.
// =================================================================================
#define HS_PITCH 65
#define SMEM_B_BYTES ((24 * 512 + 512 * HS_PITCH + 24 * HS_PITCH + 32) * 4)

__global__ void __launch_bounds__(256, 1) gru_scan_kernel(
    const float* __restrict__ Whh_f, const float* __restrict__ bhh_f,
    const float* __restrict__ Whh_b, const float* __restrict__ bhh_b)
{
    extern __shared__ float sm[];
    float* Ws  = sm;                         // [24][512]
    float* hs  = Ws + 24 * 512;              // [512][65] (k-major, pitch 65)
    float* ghs = hs + 512 * HS_PITCH;        // [24][65]
    float* bbv = ghs + 24 * HS_PITCH;        // [24]

    const int t   = threadIdx.x;
    const int blk = blockIdx.x;
    const int dir = blk >> 6;
    const int r   = blk & 63;
    const int j0  = r * 8;

    const float* Whh = dir ? Whh_b : Whh_f;
    const float* bhh = dir ? bhh_b : bhh_f;
    const float* gi  = dir ? g_gi_b : g_gi_f;
    float* hout      = dir ? g_hb : g_hf;

    // Load owned W_hh rows into smem: local row lr -> global row (lr>>3)*512 + j0 + (lr&7)
    for (int i = t; i < 24 * 512; i += 256) {
        const int lr = i >> 9, k = i & 511;
        const int grow = ((lr >> 3) << 9) + j0 + (lr & 7);
        Ws[i] = Whh[(size_t)grow * H_ + k];
    }
    if (t < 24) bbv[t] = bhh[((t >> 3) << 9) + j0 + (t & 7)];
    __syncthreads();

    const int bt = t & 63;
    const int rt = t >> 6;
    float* wr = Ws + rt * 6 * 512;

    for (int s = 0; s < S_; ++s) {
        if (s == 0) {
            for (int i = t; i < 512 * HS_PITCH; i += 256) hs[i] = 0.f;
            for (int i = t; i < 24 * HS_PITCH; i += 256) ghs[i] = 0.f;
            __syncthreads();
        } else {
            // stage h_prev transposed: hs[k][b]
            const float* hprev = hout + (size_t)(s - 1) * (B_ * H_);
#pragma unroll 4
            for (int i = 0; i < 32; i++) {
                const int l4 = t + i * 256;          // 0..8191 float4s
                const float4 v = ((const float4*)hprev)[l4];
                const int b = l4 >> 7;               // /128
                const int k = (l4 & 127) * 4;
                hs[(k + 0) * HS_PITCH + b] = v.x;
                hs[(k + 1) * HS_PITCH + b] = v.y;
                hs[(k + 2) * HS_PITCH + b] = v.z;
                hs[(k + 3) * HS_PITCH + b] = v.w;
            }
            __syncthreads();

            float acc[6] = {0.f, 0.f, 0.f, 0.f, 0.f, 0.f};
#pragma unroll 2
            for (int k4 = 0; k4 < 128; ++k4) {
                const float h0 = hs[(4 * k4 + 0) * HS_PITCH + bt];
                const float h1 = hs[(4 * k4 + 1) * HS_PITCH + bt];
                const float h2 = hs[(4 * k4 + 2) * HS_PITCH + bt];
                const float h3 = hs[(4 * k4 + 3) * HS_PITCH + bt];
#pragma unroll
                for (int i = 0; i < 6; i++) {
                    const float4 w = *(const float4*)(wr + i * 512 + 4 * k4);
                    acc[i] = fmaf(w.x, h0, fmaf(w.y, h1, fmaf(w.z, h2, fmaf(w.w, h3, acc[i]))));
                }
            }
#pragma unroll
            for (int i = 0; i < 6; i++) ghs[(rt * 6 + i) * HS_PITCH + bt] = acc[i];
            __syncthreads();
        }

        // gate combine: 8 j's x 64 b = 512 outputs, 2 per thread
        const float* gis = gi + (size_t)s * (B_ * G3);
        float* hnew = hout + (size_t)s * (B_ * H_);
#pragma unroll
        for (int q = 0; q < 2; q++) {
            const int oi = t + q * 256;
            const int i  = oi & 7;
            const int b  = oi >> 3;
            const float ir = gis[(size_t)b * G3 + j0 + i];
            const float iz = gis[(size_t)b * G3 + 512 + j0 + i];
            const float in_ = gis[(size_t)b * G3 + 1024 + j0 + i];
            const float hr = ghs[i * HS_PITCH + b] + bbv[i];
            const float hz = ghs[(8 + i) * HS_PITCH + b] + bbv[8 + i];
            const float hn = ghs[(16 + i) * HS_PITCH + b] + bbv[16 + i];
            const float hp = hs[(j0 + i) * HS_PITCH + b];
            const float rg = 1.f / (1.f + __expf(-(ir + hr)));
            const float zg = 1.f / (1.f + __expf(-(iz + hz)));
            const float ngate = tanhf(in_ + rg * hn);
            hnew[(size_t)b * H_ + j0 + i] = (1.f - zg) * ngate + zg * hp;
        }

        // grid barrier between steps (not after last)
        if (s < S_ - 1) {
            __threadfence();
            __syncthreads();
            if (t == 0) {
                const unsigned g = *(volatile unsigned*)&g_bar_gen;
                const unsigned a = atomicAdd(&g_bar_count, 1u);
                if (a == NBLK_SCAN - 1) {
                    g_bar_count = 0u;
                    __threadfence();
                    atomicAdd(&g_bar_gen, 1u);
                } else {
                    while (*(volatile unsigned*)&g_bar_gen == g) { }
                }
                __threadfence();
            }
            __syncthreads();
        }
    }
}

// =================================================================================
// Kernel C: logits = hcat @ lin_W^T + lin_b, log_softmax, transpose to [B,21,S].
// lin_W cached in smem, 16 rows per block.
// =================================================================================
#define SMEM_C_BYTES ((NCLS * 1024 + 1024 + 32) * 4)

__global__ void __launch_bounds__(256, 1) head_kernel(
    const float* __restrict__ linW,  // [21,1024]
    const float* __restrict__ linb,  // [21]
    float* __restrict__ out)         // [B,21,S]
{
    extern __shared__ float sm[];
    float* Wsm = sm;                 // 21*1024
    float* row = Wsm + NCLS * 1024;  // 1024
    float* lg  = row + 1024;         // 32

    const int t = threadIdx.x;
    for (int i = t; i < NCLS * 1024; i += 256) Wsm[i] = linW[i];
    __syncthreads();

    const int w = t >> 5, lane = t & 31;
    const int m0 = blockIdx.x * 16;

    for (int rr = 0; rr < 16; rr++) {
        const int m = m0 + rr;
        const int s = m >> 6, b = m & 63;
        const float* hf = g_hf + ((size_t)s * B_ + b) * H_;
        const float* hb = g_hb + ((size_t)(S_ - 1 - s) * B_ + b) * H_;
        ((float4*)row)[t] = (t < 128) ? ((const float4*)hf)[t]
                                      : ((const float4*)hb)[t - 128];
        __syncthreads();

#pragma unroll
        for (int j = 0; j < 3; j++) {
            const int c = w + 8 * j;
            if (c < NCLS) {
                float p = 0.f;
                const float* wc = Wsm + c * 1024;
#pragma unroll 4
                for (int k = lane; k < 1024; k += 32) p = fmaf(row[k], wc[k], p);
#pragma unroll
                for (int off = 16; off; off >>= 1) p += __shfl_xor_sync(0xffffffffu, p, off);
                if (lane == 0) lg[c] = p + linb[c];
            }
        }
        __syncthreads();
        if (t == 0) {
            float mx = lg[0];
            for (int c = 1; c < NCLS; c++) mx = fmaxf(mx, lg[c]);
            float sum = 0.f;
            for (int c = 0; c < NCLS; c++) sum += __expf(lg[c] - mx);
            lg[24] = mx + __logf(sum);
        }
        __syncthreads();
        if (t < NCLS)
            out[(size_t)b * (NCLS * S_) + (size_t)t * S_ + s] = lg[t] - lg[24];
        __syncthreads();
    }
}

// =================================================================================
extern "C" void kernel_launch(void* const* d_in, const int* in_sizes, int n_in,
                              void* d_out, int out_size)
{
    (void)in_sizes; (void)n_in; (void)out_size;
    const int*   idx     = (const int*)  d_in[0];
    const float* emb     = (const float*)d_in[1];
    const float* W_ih_f  = (const float*)d_in[2];
    const float* W_hh_f  = (const float*)d_in[3];
    const float* b_ih_f  = (const float*)d_in[4];
    const float* b_hh_f  = (const float*)d_in[5];
    const float* W_ih_b  = (const float*)d_in[6];
    const float* W_hh_b  = (const float*)d_in[7];
    const float* b_ih_b  = (const float*)d_in[8];
    const float* b_hh_b  = (const float*)d_in[9];
    const float* lin_W   = (const float*)d_in[10];
    const float* lin_b   = (const float*)d_in[11];
    float* out = (float*)d_out;

    cudaFuncSetAttribute(gru_scan_kernel, cudaFuncAttributeMaxDynamicSharedMemorySize, SMEM_B_BYTES);
    cudaFuncSetAttribute(head_kernel,     cudaFuncAttributeMaxDynamicSharedMemorySize, SMEM_C_BYTES);

    dim3 gA(24, 128);
    gi_gemm_kernel<<<gA, 256>>>(idx, emb, W_ih_f, b_ih_f, W_ih_b, b_ih_b);
    gru_scan_kernel<<<NBLK_SCAN, 256, SMEM_B_BYTES>>>(W_hh_f, b_hh_f, W_hh_b, b_hh_b);
    head_kernel<<<1024, 256, SMEM_C_BYTES>>>(lin_W, lin_b, out);
}

// round 5
// speedup vs baseline: 2.1004x; 2.1004x over previous
#include <cuda_runtime.h>
#include <math.h>
#include <stdint.h>

#define S_  256
#define B_  64
#define E_  300
#define H_  512
#define G3  1536          // 3*H
#define NCLS 21

// ---------------- scratch (device globals; no allocation allowed) ----------------
__device__ float g_gi_f[(size_t)S_ * B_ * G3];   // [s][b][1536]
__device__ float g_gi_b[(size_t)S_ * B_ * G3];   // backward, time-reversed storage
__device__ float g_hf[(size_t)S_ * B_ * H_];     // [s][b][512]
__device__ float g_hb[(size_t)S_ * B_ * H_];     // scan-time order (orig pos = S-1-t)
__device__ unsigned g_cnt2[4 * 32];              // 4 barrier groups, padded
__device__ unsigned g_gen2[4 * 32];

// =================================================================================
// Kernel A: gi = gather(emb, idx) @ W_ih^T + b_ih   (both directions)  [unchanged]
// =================================================================================
__global__ void __launch_bounds__(256, 2) gi_gemm_kernel(
    const int* __restrict__ idxmat, const float* __restrict__ emb,
    const float* __restrict__ Wf, const float* __restrict__ bf,
    const float* __restrict__ Wb, const float* __restrict__ bbias)
{
    __shared__ float As[8][128];
    __shared__ float Bs[8][128];

    const int t    = threadIdx.x;
    const int n0   = blockIdx.x * 128;
    const int m0   = blockIdx.y * 128;
    const bool bwd = (n0 >= G3);

    const int ar = t >> 1;
    const int ak = (t & 1) * 4;
    const int m  = m0 + ar;
    const int srow = m >> 6, brow = m & 63;
    const float* arow = emb + (size_t)idxmat[brow * S_ + srow] * E_;

    const int br = t >> 1;
    const int bk = ak;
    const int ng = n0 + br;
    const float* wrow = bwd ? (Wb + (size_t)(ng - G3) * E_)
                            : (Wf + (size_t)ng * E_);

    float acc[8][8];
#pragma unroll
    for (int i = 0; i < 8; i++)
#pragma unroll
        for (int j = 0; j < 8; j++) acc[i][j] = 0.f;

    const int tx = t & 15, ty = t >> 4;

    for (int k0 = 0; k0 < E_; k0 += 8) {
        float4 av = make_float4(0.f, 0.f, 0.f, 0.f);
        float4 bv = make_float4(0.f, 0.f, 0.f, 0.f);
        if (k0 + ak < E_) av = *(const float4*)(arow + k0 + ak);
        if (k0 + bk < E_) bv = *(const float4*)(wrow + k0 + bk);
        __syncthreads();
        As[ak + 0][ar] = av.x; As[ak + 1][ar] = av.y;
        As[ak + 2][ar] = av.z; As[ak + 3][ar] = av.w;
        Bs[bk + 0][br] = bv.x; Bs[bk + 1][br] = bv.y;
        Bs[bk + 2][br] = bv.z; Bs[bk + 3][br] = bv.w;
        __syncthreads();
#pragma unroll
        for (int k = 0; k < 8; k++) {
            float a[8], b[8];
            *(float4*)&a[0] = *(const float4*)&As[k][ty * 4];
            *(float4*)&a[4] = *(const float4*)&As[k][64 + ty * 4];
            *(float4*)&b[0] = *(const float4*)&Bs[k][tx * 4];
            *(float4*)&b[4] = *(const float4*)&Bs[k][64 + tx * 4];
#pragma unroll
            for (int i = 0; i < 8; i++)
#pragma unroll
                for (int j = 0; j < 8; j++)
                    acc[i][j] = fmaf(a[i], b[j], acc[i][j]);
        }
    }

    const float* bias = bwd ? bbias : bf;
    float* gbase = bwd ? g_gi_b : g_gi_f;
    const int nc0 = (bwd ? n0 - G3 : n0) + tx * 4;

#pragma unroll
    for (int i = 0; i < 8; i++) {
        const int mi = m0 + ((i < 4) ? (ty * 4 + i) : (64 + ty * 4 + i - 4));
        const int si = mi >> 6, bi = mi & 63;
        const size_t mrow = bwd ? ((size_t)(S_ - 1 - si) * B_ + bi) : (size_t)mi;
        float* dst = gbase + mrow * G3;
        float4 v0, v1;
        v0.x = acc[i][0] + bias[nc0 + 0];
        v0.y = acc[i][1] + bias[nc0 + 1];
        v0.z = acc[i][2] + bias[nc0 + 2];
        v0.w = acc[i][3] + bias[nc0 + 3];
        v1.x = acc[i][4] + bias[nc0 + 64 + 0];
        v1.y = acc[i][5] + bias[nc0 + 64 + 1];
        v1.z = acc[i][6] + bias[nc0 + 64 + 2];
        v1.w = acc[i][7] + bias[nc0 + 64 + 3];
        *(float4*)(dst + nc0)      = v0;
        *(float4*)(dst + nc0 + 64) = v1;
    }
}

// =================================================================================
// Kernel B: persistent bidirectional GRU scan with tf32 mma.sync.
// 128 blocks = dir(2) x jblk(32: 16 units -> 48 gate rows) x bhalf(2: 32 batch).
// 12 warps = gate g(3) x K-quarter kg(4). W A-frags register-resident all steps.
// smem: h tile [32][516] fp32 (straight copy, no transpose) + partial buf.
// 4 independent 32-block barriers (dir x bhalf).
// =================================================================================
#define HSP 516                 // h smem pitch (floats): (4n+k)%32 conflict-free
#define BUFP 34                 // partial buffer pitch
#define SMEM_B_BYTES ((32 * HSP + 4 * 48 * BUFP) * 4)

__device__ __forceinline__ void mma_tf32(float c[4],
    uint32_t a0, uint32_t a1, uint32_t a2, uint32_t a3,
    uint32_t b0, uint32_t b1)
{
    asm volatile(
        "mma.sync.aligned.m16n8k8.row.col.f32.tf32.tf32.f32 "
        "{%0,%1,%2,%3},{%4,%5,%6,%7},{%8,%9},{%0,%1,%2,%3};"
        : "+f"(c[0]), "+f"(c[1]), "+f"(c[2]), "+f"(c[3])
        : "r"(a0), "r"(a1), "r"(a2), "r"(a3), "r"(b0), "r"(b1));
}

__device__ __forceinline__ uint32_t f2tf32(float v) {
    uint32_t r;
    asm("cvt.rna.tf32.f32 %0, %1;" : "=r"(r) : "f"(v));
    return r;
}

__global__ void __launch_bounds__(384, 1) gru_scan_kernel(
    const float* __restrict__ Whh_f, const float* __restrict__ bhh_f,
    const float* __restrict__ Whh_b, const float* __restrict__ bhh_b)
{
    extern __shared__ float sm[];
    float* hs  = sm;                 // [32][HSP] h tile (fp32, exact)
    float* buf = hs + 32 * HSP;      // [4*48][BUFP] mma partials
    __shared__ float bbv[48];
    __shared__ unsigned sbase;

    const int t    = threadIdx.x;
    const int lane = t & 31;
    const int w    = t >> 5;          // 0..11
    const int gq   = lane >> 2;       // groupID 0..7
    const int tig  = lane & 3;        // thread-in-group

    const int blk   = blockIdx.x;
    const int dir   = blk >> 6;
    const int r     = blk & 63;
    const int jblk  = r >> 1;
    const int bhalf = r & 1;
    const int j0    = jblk * 16;
    const int b0    = bhalf * 32;
    const int grp   = dir * 2 + bhalf;   // barrier group (32 members)

    const float* Whh = dir ? Whh_b : Whh_f;
    const float* bhh = dir ? bhh_b : bhh_f;
    const float* gi  = dir ? g_gi_b : g_gi_f;
    float* hout      = dir ? g_hb : g_hf;

    // warp role
    const int kg = w & 3;       // K quarter
    const int g  = w >> 2;      // gate 0=r 1=z 2=n

    // ---- prologue: biases, barrier base, register-resident W A-fragments ----
    if (t < 48) bbv[t] = bhh[(size_t)((t >> 4) * 512 + j0 + (t & 15))];
    if (t == 0) sbase = *(volatile unsigned*)&g_gen2[grp * 32];

    uint32_t a[16][4];
    {
        const float* Wg = Whh + ((size_t)(g * 512 + j0)) * 512;
#pragma unroll
        for (int kt = 0; kt < 16; kt++) {
            const int col = kg * 128 + kt * 8 + tig;
            a[kt][0] = f2tf32(Wg[(size_t)gq * 512 + col]);
            a[kt][1] = f2tf32(Wg[(size_t)(gq + 8) * 512 + col]);
            a[kt][2] = f2tf32(Wg[(size_t)gq * 512 + col + 4]);
            a[kt][3] = f2tf32(Wg[(size_t)(gq + 8) * 512 + col + 4]);
        }
    }
    __syncthreads();

    for (int s = 0; s < S_; ++s) {
        if (s > 0) {
            // stage h_prev rows [b0, b0+32), full k: straight float4 copy
            const float4* hp4 = (const float4*)(hout + (size_t)(s - 1) * (B_ * H_)
                                                + (size_t)b0 * H_);
#pragma unroll 4
            for (int i = t; i < 4096; i += 384) {
                const int b = i >> 7, k4 = i & 127;
                *(float4*)(hs + b * HSP + k4 * 4) = hp4[b * 128 + k4];
            }
            __syncthreads();

            // mma: gh partial [48 rows x 32 b] for this warp's (g, kg)
            float acc[4][4];
#pragma unroll
            for (int nt = 0; nt < 4; nt++)
#pragma unroll
                for (int i = 0; i < 4; i++) acc[nt][i] = 0.f;

            const int kbase = kg * 128;
#pragma unroll
            for (int kt = 0; kt < 16; kt++) {
                const int kk = kbase + kt * 8 + tig;
#pragma unroll
                for (int nt = 0; nt < 4; nt++) {
                    const float* hb = hs + (nt * 8 + gq) * HSP;
                    const uint32_t bb0 = __float_as_uint(hb[kk]);
                    const uint32_t bb1 = __float_as_uint(hb[kk + 4]);
                    mma_tf32(acc[nt], a[kt][0], a[kt][1], a[kt][2], a[kt][3], bb0, bb1);
                }
            }
            // store partials: row = g*16 + gq(+8), col = nt*8 + 2*tig(+1)
            float* bb = buf + (size_t)(kg * 48 + g * 16) * BUFP;
#pragma unroll
            for (int nt = 0; nt < 4; nt++) {
                const int c = nt * 8 + 2 * tig;
                bb[gq * BUFP + c]           = acc[nt][0];
                bb[gq * BUFP + c + 1]       = acc[nt][1];
                bb[(gq + 8) * BUFP + c]     = acc[nt][2];
                bb[(gq + 8) * BUFP + c + 1] = acc[nt][3];
            }
            __syncthreads();
        }

        // ---- gate combine: 16 j x 32 b = 512 outputs ----
        const float* gis = gi + (size_t)s * (B_ * G3);
        float* hnew = hout + (size_t)s * (B_ * H_);
        for (int o = t; o < 512; o += 384) {
            const int j = o & 15;
            const int b = o >> 4;
            float rs = 0.f, zs = 0.f, ns = 0.f, hp = 0.f;
            if (s > 0) {
#pragma unroll
                for (int q = 0; q < 4; q++) {
                    rs += buf[(q * 48 + j) * BUFP + b];
                    zs += buf[(q * 48 + 16 + j) * BUFP + b];
                    ns += buf[(q * 48 + 32 + j) * BUFP + b];
                }
                hp = hs[b * HSP + j0 + j];
            }
            const size_t gb = (size_t)(b0 + b) * G3 + j0 + j;
            const float ir  = gis[gb];
            const float iz  = gis[gb + 512];
            const float in_ = gis[gb + 1024];
            const float hr = rs + bbv[j];
            const float hz = zs + bbv[16 + j];
            const float hn = ns + bbv[32 + j];
            const float rg = 1.f / (1.f + __expf(-(ir + hr)));
            const float zg = 1.f / (1.f + __expf(-(iz + hz)));
            const float ng = tanhf(in_ + rg * hn);
            hnew[(size_t)(b0 + b) * H_ + j0 + j] = (1.f - zg) * ng + zg * hp;
        }

        // ---- group barrier (32 blocks of same dir x bhalf) ----
        if (s < S_ - 1) {
            __threadfence();
            __syncthreads();
            if (t == 0) {
                const unsigned tgt = sbase + (unsigned)s + 1u;
                const unsigned arr = atomicAdd(&g_cnt2[grp * 32], 1u);
                if (arr == 31u) {
                    g_cnt2[grp * 32] = 0u;
                    __threadfence();
                    atomicAdd(&g_gen2[grp * 32], 1u);
                } else {
                    while (*(volatile unsigned*)&g_gen2[grp * 32] < tgt) { }
                }
                __threadfence();
            }
            __syncthreads();
        }
    }
}

// =================================================================================
// Kernel C: logits + log_softmax + transpose to [B,21,S]  [unchanged]
// =================================================================================
#define SMEM_C_BYTES ((NCLS * 1024 + 1024 + 32) * 4)

__global__ void __launch_bounds__(256, 1) head_kernel(
    const float* __restrict__ linW, const float* __restrict__ linb,
    float* __restrict__ out)
{
    extern __shared__ float sm[];
    float* Wsm = sm;
    float* row = Wsm + NCLS * 1024;
    float* lg  = row + 1024;

    const int t = threadIdx.x;
    for (int i = t; i < NCLS * 1024; i += 256) Wsm[i] = linW[i];
    __syncthreads();

    const int w = t >> 5, lane = t & 31;
    const int m0 = blockIdx.x * 16;

    for (int rr = 0; rr < 16; rr++) {
        const int m = m0 + rr;
        const int s = m >> 6, b = m & 63;
        const float* hf = g_hf + ((size_t)s * B_ + b) * H_;
        const float* hb = g_hb + ((size_t)(S_ - 1 - s) * B_ + b) * H_;
        ((float4*)row)[t] = (t < 128) ? ((const float4*)hf)[t]
                                      : ((const float4*)hb)[t - 128];
        __syncthreads();

#pragma unroll
        for (int j = 0; j < 3; j++) {
            const int c = w + 8 * j;
            if (c < NCLS) {
                float p = 0.f;
                const float* wc = Wsm + c * 1024;
#pragma unroll 4
                for (int k = lane; k < 1024; k += 32) p = fmaf(row[k], wc[k], p);
#pragma unroll
                for (int off = 16; off; off >>= 1) p += __shfl_xor_sync(0xffffffffu, p, off);
                if (lane == 0) lg[c] = p + linb[c];
            }
        }
        __syncthreads();
        if (t == 0) {
            float mx = lg[0];
            for (int c = 1; c < NCLS; c++) mx = fmaxf(mx, lg[c]);
            float sum = 0.f;
            for (int c = 0; c < NCLS; c++) sum += __expf(lg[c] - mx);
            lg[24] = mx + __logf(sum);
        }
        __syncthreads();
        if (t < NCLS)
            out[(size_t)b * (NCLS * S_) + (size_t)t * S_ + s] = lg[t] - lg[24];
        __syncthreads();
    }
}

// =================================================================================
extern "C" void kernel_launch(void* const* d_in, const int* in_sizes, int n_in,
                              void* d_out, int out_size)
{
    (void)in_sizes; (void)n_in; (void)out_size;
    const int*   idx     = (const int*)  d_in[0];
    const float* emb     = (const float*)d_in[1];
    const float* W_ih_f  = (const float*)d_in[2];
    const float* W_hh_f  = (const float*)d_in[3];
    const float* b_ih_f  = (const float*)d_in[4];
    const float* b_hh_f  = (const float*)d_in[5];
    const float* W_ih_b  = (const float*)d_in[6];
    const float* W_hh_b  = (const float*)d_in[7];
    const float* b_ih_b  = (const float*)d_in[8];
    const float* b_hh_b  = (const float*)d_in[9];
    const float* lin_W   = (const float*)d_in[10];
    const float* lin_b   = (const float*)d_in[11];
    float* out = (float*)d_out;

    cudaFuncSetAttribute(gru_scan_kernel, cudaFuncAttributeMaxDynamicSharedMemorySize, SMEM_B_BYTES);
    cudaFuncSetAttribute(head_kernel,     cudaFuncAttributeMaxDynamicSharedMemorySize, SMEM_C_BYTES);

    dim3 gA(24, 128);
    gi_gemm_kernel<<<gA, 256>>>(idx, emb, W_ih_f, b_ih_f, W_ih_b, b_ih_b);
    gru_scan_kernel<<<128, 384, SMEM_B_BYTES>>>(W_hh_f, b_hh_f, W_hh_b, b_hh_b);
    head_kernel<<<1024, 256, SMEM_C_BYTES>>>(lin_W, lin_b, out);
}

// round 6
// speedup vs baseline: 2.8439x; 1.3540x over previous
#include <cuda_runtime.h>
#include <math.h>
#include <stdint.h>

#define S_  256
#define B_  64
#define E_  300
#define H_  512
#define G3  1536          // 3*H
#define NCLS 21

// ---------------- scratch (device globals; no allocation allowed) ----------------
__device__ float g_gi_f[(size_t)S_ * B_ * G3];   // [s][b][1536]
__device__ float g_gi_b[(size_t)S_ * B_ * G3];   // backward, time-reversed storage
__device__ float g_hf[(size_t)S_ * B_ * H_];     // [s][b][512]
__device__ float g_hb[(size_t)S_ * B_ * H_];     // scan-time order (orig pos = S-1-t)
__device__ unsigned g_cnt2[4 * 32];              // 4 barrier groups, padded
__device__ unsigned g_gen2[4 * 32];

// ---------------- common helpers ----------------
__device__ __forceinline__ void mma_tf32(float c[4],
    uint32_t a0, uint32_t a1, uint32_t a2, uint32_t a3,
    uint32_t b0, uint32_t b1)
{
    asm volatile(
        "mma.sync.aligned.m16n8k8.row.col.f32.tf32.tf32.f32 "
        "{%0,%1,%2,%3},{%4,%5,%6,%7},{%8,%9},{%0,%1,%2,%3};"
        : "+f"(c[0]), "+f"(c[1]), "+f"(c[2]), "+f"(c[3])
        : "r"(a0), "r"(a1), "r"(a2), "r"(a3), "r"(b0), "r"(b1));
}

__device__ __forceinline__ uint32_t f2tf32(float v) {
    uint32_t r;
    asm("cvt.rna.tf32.f32 %0, %1;" : "=r"(r) : "f"(v));
    return r;
}

__device__ __forceinline__ unsigned atom_add_release(unsigned* p, unsigned v) {
    unsigned old;
    asm volatile("atom.add.release.gpu.global.u32 %0,[%1],%2;"
                 : "=r"(old) : "l"(p), "r"(v) : "memory");
    return old;
}

__device__ __forceinline__ unsigned ld_acquire(unsigned* p) {
    unsigned v;
    asm volatile("ld.acquire.gpu.global.u32 %0,[%1];" : "=r"(v) : "l"(p) : "memory");
    return v;
}

__device__ __forceinline__ float sigm_f(float x) {
    return __fdividef(1.f, 1.f + __expf(-x));
}
__device__ __forceinline__ float tanh_f(float x) {
    const float ax = fabsf(x);
    const float e  = __expf(-2.f * ax);
    const float r  = __fdividef(1.f - e, 1.f + e);
    return copysignf(r, x);
}

// =================================================================================
// Kernel A: gi = gather(emb, idx) @ W_ih^T + b_ih  — tf32 tensor-core GEMM.
// M=16384, N=3072 (fwd|bwd), K=300 (padded 304). 128x128 tile, BK=16, 8 warps,
// warp tile 32x64 (2 m16 x 8 n8). smem [k][mn] pitch 136 => conflict-free frags.
// =================================================================================
#define AP 136

__global__ void __launch_bounds__(256, 2) gi_gemm_kernel(
    const int* __restrict__ idxmat, const float* __restrict__ emb,
    const float* __restrict__ Wf, const float* __restrict__ bf,
    const float* __restrict__ Wb, const float* __restrict__ bbias)
{
    __shared__ uint32_t As[16][AP];
    __shared__ uint32_t Bs[16][AP];

    const int t    = threadIdx.x;
    const int n0   = blockIdx.x * 128;
    const int m0   = blockIdx.y * 128;
    const bool bwd = (n0 >= G3);

    // loader: row = t&127, k-half = (t>>7)*8
    const int lr = t & 127;
    const int lk = (t >> 7) * 8;

    const int am = m0 + lr;
    const int srow = am >> 6, brow = am & 63;
    const float* arow = emb + (size_t)idxmat[brow * S_ + srow] * E_;

    const int ng = n0 + lr;
    const float* wrow = bwd ? (Wb + (size_t)(ng - G3) * E_)
                            : (Wf + (size_t)ng * E_);

    const int lane = t & 31;
    const int w    = t >> 5;
    const int gq   = lane >> 2, tig = lane & 3;
    const int mw   = (w & 3) * 32;
    const int nw   = (w >> 2) * 64;

    float acc[2][8][4];
#pragma unroll
    for (int mt = 0; mt < 2; mt++)
#pragma unroll
        for (int nt = 0; nt < 8; nt++)
#pragma unroll
            for (int i = 0; i < 4; i++) acc[mt][nt][i] = 0.f;

    const float4 z4 = make_float4(0.f, 0.f, 0.f, 0.f);

    for (int k0 = 0; k0 < 304; k0 += 16) {
        const int ka = k0 + lk;
        float4 av0 = (ka     < E_) ? *(const float4*)(arow + ka)     : z4;
        float4 av1 = (ka + 4 < E_) ? *(const float4*)(arow + ka + 4) : z4;
        float4 bv0 = (ka     < E_) ? *(const float4*)(wrow + ka)     : z4;
        float4 bv1 = (ka + 4 < E_) ? *(const float4*)(wrow + ka + 4) : z4;
        __syncthreads();
        As[lk + 0][lr] = f2tf32(av0.x); As[lk + 1][lr] = f2tf32(av0.y);
        As[lk + 2][lr] = f2tf32(av0.z); As[lk + 3][lr] = f2tf32(av0.w);
        As[lk + 4][lr] = f2tf32(av1.x); As[lk + 5][lr] = f2tf32(av1.y);
        As[lk + 6][lr] = f2tf32(av1.z); As[lk + 7][lr] = f2tf32(av1.w);
        Bs[lk + 0][lr] = f2tf32(bv0.x); Bs[lk + 1][lr] = f2tf32(bv0.y);
        Bs[lk + 2][lr] = f2tf32(bv0.z); Bs[lk + 3][lr] = f2tf32(bv0.w);
        Bs[lk + 4][lr] = f2tf32(bv1.x); Bs[lk + 5][lr] = f2tf32(bv1.y);
        Bs[lk + 6][lr] = f2tf32(bv1.z); Bs[lk + 7][lr] = f2tf32(bv1.w);
        __syncthreads();

#pragma unroll
        for (int kt = 0; kt < 2; kt++) {
            const int kb = kt * 8;
            uint32_t a[2][4];
#pragma unroll
            for (int mt = 0; mt < 2; mt++) {
                const int mb = mw + mt * 16;
                a[mt][0] = As[kb + tig][mb + gq];
                a[mt][1] = As[kb + tig][mb + gq + 8];
                a[mt][2] = As[kb + tig + 4][mb + gq];
                a[mt][3] = As[kb + tig + 4][mb + gq + 8];
            }
#pragma unroll
            for (int nt = 0; nt < 8; nt++) {
                const int nb = nw + nt * 8 + gq;
                const uint32_t b0 = Bs[kb + tig][nb];
                const uint32_t b1 = Bs[kb + tig + 4][nb];
                mma_tf32(acc[0][nt], a[0][0], a[0][1], a[0][2], a[0][3], b0, b1);
                mma_tf32(acc[1][nt], a[1][0], a[1][1], a[1][2], a[1][3], b0, b1);
            }
        }
    }

    const float* bias = bwd ? bbias : bf;
    float* gbase = bwd ? g_gi_b : g_gi_f;
    const int nc0 = (bwd ? n0 - G3 : n0) + nw;

#pragma unroll
    for (int mt = 0; mt < 2; mt++) {
#pragma unroll
        for (int half = 0; half < 2; half++) {
            const int rm = m0 + mw + mt * 16 + gq + half * 8;
            const int si = rm >> 6, bi = rm & 63;
            const size_t mrow = bwd ? ((size_t)(S_ - 1 - si) * B_ + bi) : (size_t)rm;
            float* dst = gbase + mrow * G3;
#pragma unroll
            for (int nt = 0; nt < 8; nt++) {
                const int c = nc0 + nt * 8 + 2 * tig;
                float2 v;
                v.x = acc[mt][nt][half * 2 + 0] + bias[c];
                v.y = acc[mt][nt][half * 2 + 1] + bias[c + 1];
                *(float2*)(dst + c) = v;
            }
        }
    }
}

// =================================================================================
// Kernel B: persistent bidirectional GRU scan with tf32 mma.sync.
// 128 blocks = dir(2) x jblk(32) x bhalf(2). 12 warps = gate(3) x K-quarter(4).
// acquire/release group barrier (no threadfence); gi prefetched before the wait.
// =================================================================================
#define HSP 516
#define BUFP 34
#define SMEM_B_BYTES ((32 * HSP + 4 * 48 * BUFP) * 4)

__global__ void __launch_bounds__(384, 1) gru_scan_kernel(
    const float* __restrict__ Whh_f, const float* __restrict__ bhh_f,
    const float* __restrict__ Whh_b, const float* __restrict__ bhh_b)
{
    extern __shared__ float sm[];
    float* hs  = sm;                 // [32][HSP] h tile (fp32, exact)
    float* buf = hs + 32 * HSP;      // [4*48][BUFP] mma partials
    __shared__ float bbv[48];
    __shared__ unsigned sbase;

    const int t    = threadIdx.x;
    const int lane = t & 31;
    const int w    = t >> 5;
    const int gq   = lane >> 2;
    const int tig  = lane & 3;

    const int blk   = blockIdx.x;
    const int dir   = blk >> 6;
    const int r     = blk & 63;
    const int jblk  = r >> 1;
    const int bhalf = r & 1;
    const int j0    = jblk * 16;
    const int b0    = bhalf * 32;
    const int grp   = dir * 2 + bhalf;

    const float* Whh = dir ? Whh_b : Whh_f;
    const float* bhh = dir ? bhh_b : bhh_f;
    const float* gi  = dir ? g_gi_b : g_gi_f;
    float* hout      = dir ? g_hb : g_hf;

    const int kg = w & 3;
    const int g  = w >> 2;

    if (t < 48) bbv[t] = bhh[(size_t)((t >> 4) * 512 + j0 + (t & 15))];
    if (t == 0) sbase = *(volatile unsigned*)&g_gen2[grp * 32];

    uint32_t a[16][4];
    {
        const float* Wg = Whh + ((size_t)(g * 512 + j0)) * 512;
#pragma unroll
        for (int kt = 0; kt < 16; kt++) {
            const int col = kg * 128 + kt * 8 + tig;
            a[kt][0] = f2tf32(Wg[(size_t)gq * 512 + col]);
            a[kt][1] = f2tf32(Wg[(size_t)(gq + 8) * 512 + col]);
            a[kt][2] = f2tf32(Wg[(size_t)gq * 512 + col + 4]);
            a[kt][3] = f2tf32(Wg[(size_t)(gq + 8) * 512 + col + 4]);
        }
    }
    __syncthreads();

    // per-thread gate-combine coordinates (o = t and o = t+384 if t<128)
    const int j1 = t & 15,          b1 = t >> 4;
    const int j2 = (t + 384) & 15,  b2 = (t + 384) >> 4;

    for (int s = 0; s < S_; ++s) {
        // ---- prefetch gi[s] (independent of h -> overlaps barrier wait) ----
        const float* gis = gi + (size_t)s * (B_ * G3);
        const size_t ga1 = (size_t)(b0 + b1) * G3 + j0 + j1;
        const float ir0 = gis[ga1];
        const float iz0 = gis[ga1 + 512];
        const float in0 = gis[ga1 + 1024];
        float ir1 = 0.f, iz1 = 0.f, in1 = 0.f;
        if (t < 128) {
            const size_t ga2 = (size_t)(b0 + b2) * G3 + j0 + j2;
            ir1 = gis[ga2]; iz1 = gis[ga2 + 512]; in1 = gis[ga2 + 1024];
        }

        if (s > 0) {
            // ---- wait for h[s-1] from all 32 group blocks ----
            if (t == 0) {
                const unsigned tgt = sbase + (unsigned)s;
                while (ld_acquire(&g_gen2[grp * 32]) < tgt) { }
            }
            __syncthreads();

            // ---- stage h_prev rows [b0, b0+32) ----
            const float4* hp4 = (const float4*)(hout + (size_t)(s - 1) * (B_ * H_)
                                                + (size_t)b0 * H_);
#pragma unroll 4
            for (int i = t; i < 4096; i += 384) {
                const int b = i >> 7, k4 = i & 127;
                *(float4*)(hs + b * HSP + k4 * 4) = hp4[b * 128 + k4];
            }
            __syncthreads();

            // ---- mma partials ----
            float acc[4][4];
#pragma unroll
            for (int nt = 0; nt < 4; nt++)
#pragma unroll
                for (int i = 0; i < 4; i++) acc[nt][i] = 0.f;

            const int kbase = kg * 128;
#pragma unroll
            for (int kt = 0; kt < 16; kt++) {
                const int kk = kbase + kt * 8 + tig;
#pragma unroll
                for (int nt = 0; nt < 4; nt++) {
                    const float* hb = hs + (nt * 8 + gq) * HSP;
                    const uint32_t bb0 = __float_as_uint(hb[kk]);
                    const uint32_t bb1 = __float_as_uint(hb[kk + 4]);
                    mma_tf32(acc[nt], a[kt][0], a[kt][1], a[kt][2], a[kt][3], bb0, bb1);
                }
            }
            float* bb = buf + (size_t)(kg * 48 + g * 16) * BUFP;
#pragma unroll
            for (int nt = 0; nt < 4; nt++) {
                const int c = nt * 8 + 2 * tig;
                bb[gq * BUFP + c]           = acc[nt][0];
                bb[gq * BUFP + c + 1]       = acc[nt][1];
                bb[(gq + 8) * BUFP + c]     = acc[nt][2];
                bb[(gq + 8) * BUFP + c + 1] = acc[nt][3];
            }
            __syncthreads();
        }

        // ---- gate combine: output 1 (o = t) ----
        float* hnew = hout + (size_t)s * (B_ * H_);
        {
            float rs = 0.f, zs = 0.f, ns = 0.f, hp = 0.f;
            if (s > 0) {
#pragma unroll
                for (int q = 0; q < 4; q++) {
                    rs += buf[(q * 48 + j1) * BUFP + b1];
                    zs += buf[(q * 48 + 16 + j1) * BUFP + b1];
                    ns += buf[(q * 48 + 32 + j1) * BUFP + b1];
                }
                hp = hs[b1 * HSP + j0 + j1];
            }
            const float rg = sigm_f(ir0 + rs + bbv[j1]);
            const float zg = sigm_f(iz0 + zs + bbv[16 + j1]);
            const float ng = tanh_f(in0 + rg * (ns + bbv[32 + j1]));
            hnew[(size_t)(b0 + b1) * H_ + j0 + j1] = (1.f - zg) * ng + zg * hp;
        }
        // ---- gate combine: output 2 (o = t + 384, t < 128) ----
        if (t < 128) {
            float rs = 0.f, zs = 0.f, ns = 0.f, hp = 0.f;
            if (s > 0) {
#pragma unroll
                for (int q = 0; q < 4; q++) {
                    rs += buf[(q * 48 + j2) * BUFP + b2];
                    zs += buf[(q * 48 + 16 + j2) * BUFP + b2];
                    ns += buf[(q * 48 + 32 + j2) * BUFP + b2];
                }
                hp = hs[b2 * HSP + j0 + j2];
            }
            const float rg = sigm_f(ir1 + rs + bbv[j2]);
            const float zg = sigm_f(iz1 + zs + bbv[16 + j2]);
            const float ng = tanh_f(in1 + rg * (ns + bbv[32 + j2]));
            hnew[(size_t)(b0 + b2) * H_ + j0 + j2] = (1.f - zg) * ng + zg * hp;
        }

        // ---- arrive (release) ----
        if (s < S_ - 1) {
            __syncthreads();
            if (t == 0) {
                const unsigned old = atom_add_release(&g_cnt2[grp * 32], 1u);
                if (old == 31u) {
                    *(volatile unsigned*)&g_cnt2[grp * 32] = 0u;
                    atom_add_release(&g_gen2[grp * 32], 1u);
                }
            }
        }
    }
}

// =================================================================================
// Kernel C: logits + log_softmax + transpose to [B,21,S]  [unchanged]
// =================================================================================
#define SMEM_C_BYTES ((NCLS * 1024 + 1024 + 32) * 4)

__global__ void __launch_bounds__(256, 1) head_kernel(
    const float* __restrict__ linW, const float* __restrict__ linb,
    float* __restrict__ out)
{
    extern __shared__ float sm[];
    float* Wsm = sm;
    float* row = Wsm + NCLS * 1024;
    float* lg  = row + 1024;

    const int t = threadIdx.x;
    for (int i = t; i < NCLS * 1024; i += 256) Wsm[i] = linW[i];
    __syncthreads();

    const int w = t >> 5, lane = t & 31;
    const int m0 = blockIdx.x * 16;

    for (int rr = 0; rr < 16; rr++) {
        const int m = m0 + rr;
        const int s = m >> 6, b = m & 63;
        const float* hf = g_hf + ((size_t)s * B_ + b) * H_;
        const float* hb = g_hb + ((size_t)(S_ - 1 - s) * B_ + b) * H_;
        ((float4*)row)[t] = (t < 128) ? ((const float4*)hf)[t]
                                      : ((const float4*)hb)[t - 128];
        __syncthreads();

#pragma unroll
        for (int j = 0; j < 3; j++) {
            const int c = w + 8 * j;
            if (c < NCLS) {
                float p = 0.f;
                const float* wc = Wsm + c * 1024;
#pragma unroll 4
                for (int k = lane; k < 1024; k += 32) p = fmaf(row[k], wc[k], p);
#pragma unroll
                for (int off = 16; off; off >>= 1) p += __shfl_xor_sync(0xffffffffu, p, off);
                if (lane == 0) lg[c] = p + linb[c];
            }
        }
        __syncthreads();
        if (t == 0) {
            float mx = lg[0];
            for (int c = 1; c < NCLS; c++) mx = fmaxf(mx, lg[c]);
            float sum = 0.f;
            for (int c = 0; c < NCLS; c++) sum += __expf(lg[c] - mx);
            lg[24] = mx + __logf(sum);
        }
        __syncthreads();
        if (t < NCLS)
            out[(size_t)b * (NCLS * S_) + (size_t)t * S_ + s] = lg[t] - lg[24];
        __syncthreads();
    }
}

// =================================================================================
extern "C" void kernel_launch(void* const* d_in, const int* in_sizes, int n_in,
                              void* d_out, int out_size)
{
    (void)in_sizes; (void)n_in; (void)out_size;
    const int*   idx     = (const int*)  d_in[0];
    const float* emb     = (const float*)d_in[1];
    const float* W_ih_f  = (const float*)d_in[2];
    const float* W_hh_f  = (const float*)d_in[3];
    const float* b_ih_f  = (const float*)d_in[4];
    const float* b_hh_f  = (const float*)d_in[5];
    const float* W_ih_b  = (const float*)d_in[6];
    const float* W_hh_b  = (const float*)d_in[7];
    const float* b_ih_b  = (const float*)d_in[8];
    const float* b_hh_b  = (const float*)d_in[9];
    const float* lin_W   = (const float*)d_in[10];
    const float* lin_b   = (const float*)d_in[11];
    float* out = (float*)d_out;

    cudaFuncSetAttribute(gru_scan_kernel, cudaFuncAttributeMaxDynamicSharedMemorySize, SMEM_B_BYTES);
    cudaFuncSetAttribute(head_kernel,     cudaFuncAttributeMaxDynamicSharedMemorySize, SMEM_C_BYTES);

    dim3 gA(24, 128);
    gi_gemm_kernel<<<gA, 256>>>(idx, emb, W_ih_f, b_ih_f, W_ih_b, b_ih_b);
    gru_scan_kernel<<<128, 384, SMEM_B_BYTES>>>(W_hh_f, b_hh_f, W_hh_b, b_hh_b);
    head_kernel<<<1024, 256, SMEM_C_BYTES>>>(lin_W, lin_b, out);
}